// round 11
// baseline (speedup 1.0000x reference)
#include <cuda_runtime.h>
#include <math.h>
#include <stdint.h>

#define N_   8
#define C_   64
#define H_   256
#define W_   256
#define K2_  9
#define NBLK 512
#define QELEMS (H_ * W_ / 4)
#define TPITCH 260                      // smem tile row pitch (floats), 1040B

// scratch (no cudaMalloc allowed); all counters monotonic => graph-replay safe
__device__ float g_part[N_ * C_ * 4];            // quarter-plane raw sums
__device__ unsigned int g_done[N_];              // pool completions per sample
__device__ unsigned int g_epoch_blk[NBLK];       // per-block replay counter

__device__ __forceinline__ void cp16(uint32_t dst, const void* src) {
    asm volatile("cp.async.cg.shared.global [%0], [%1], 16;" :: "r"(dst), "l"(src));
}
__device__ __forceinline__ void cp_commit() {
    asm volatile("cp.async.commit_group;");
}
template <int N>
__device__ __forceinline__ void cp_wait() {
    asm volatile("cp.async.wait_group %0;" :: "n"(N));
}

// ---------------------------------------------------------------------------
// Stage one 18-row x 256-col slab (16 output rows + reflect halo) into smem.
// 1152 x 16B cp.async: zero register cost, massive MLP.
// ---------------------------------------------------------------------------
__device__ __forceinline__ void load_subtile(uint32_t buf_addr,
                                             const float* __restrict__ xp,
                                             int y0, int tid) {
    #pragma unroll
    for (int it = 0; it < 5; ++it) {
        const int j = tid + (it << 8);
        if (j < 18 * 64) {
            const int rr = j >> 6;
            const int cc = j & 63;
            int gr = y0 - 1 + rr;
            gr = gr < 0 ? 1 : (gr >= H_ ? 2 * H_ - 2 - gr : gr);
            cp16(buf_addr + rr * (TPITCH * 4) + cc * 16,
                 xp + (size_t)gr * W_ + cc * 4);
        }
    }
    cp_commit();
}

// ---------------------------------------------------------------------------
// Compute one 16x256 subtile from a staged smem slab (smem row s = y0-1+s).
// Warp w: 4-row band (w>>1), 128-col half (w&1); thread: 4 cols, rolling
// 3x6 window from smem; reflect columns resolved by direct smem indexing.
// ---------------------------------------------------------------------------
__device__ __forceinline__ void compute_subtile(
        const float* __restrict__ tile, float* __restrict__ ob0,
        const float* wlfk, float A, float Bc, float lh1,
        int warp, int lane) {
    const int band = warp >> 1;
    const int half = warp & 1;
    const int cb   = half * 128 + lane * 4;
    const int sr0  = band * 4;                // first smem row of 6

    const float w0 = wlfk[0], w1 = wlfk[1], w2 = wlfk[2];
    const float w3 = wlfk[3], w4 = wlfk[4], w5 = wlfk[5];
    const float w6 = wlfk[6], w7 = wlfk[7], w8 = wlfk[8];

    float win[3][6];
    #define LDROW(SR, D) do {                                          \
        const float* rp = tile + (SR) * TPITCH + cb;                   \
        float4 v = *(const float4*)rp;                                 \
        (D)[1] = v.x; (D)[2] = v.y; (D)[3] = v.z; (D)[4] = v.w;        \
        (D)[0] = (cb == 0)   ? rp[1] : rp[-1];                         \
        (D)[5] = (cb == 252) ? rp[2] : rp[4];                          \
    } while (0)

    LDROW(sr0,     win[0]);
    LDROW(sr0 + 1, win[1]);

    float* ob = ob0 + (size_t)(band * 4) * W_ + cb;

    #pragma unroll
    for (int k = 0; k < 4; ++k) {
        LDROW(sr0 + 2 + k, win[(k + 2) % 3]);
        const float* t0 = win[k % 3];
        const float* t1 = win[(k + 1) % 3];
        const float* t2 = win[(k + 2) % 3];
        float o[4];
        #pragma unroll
        for (int j = 0; j < 4; ++j) {
            float acc;
            acc = w0 * t0[j];
            acc = fmaf(w1, t0[j + 1], acc);
            acc = fmaf(w2, t0[j + 2], acc);
            acc = fmaf(w3, t1[j],     acc);
            acc = fmaf(w4, t1[j + 1], acc);
            acc = fmaf(w5, t1[j + 2], acc);
            acc = fmaf(w6, t2[j],     acc);
            acc = fmaf(w7, t2[j + 1], acc);
            acc = fmaf(w8, t2[j + 2], acc);
            o[j] = fmaf(acc, A, fmaf(t1[j + 1], lh1, Bc));
        }
        __stcs((float4*)(ob + (size_t)k * W_),
               make_float4(o[0], o[1], o[2], o[3]));
    }
    #undef LDROW
}

// ---------------------------------------------------------------------------
// Group-decoupled pipeline (sample g owned by 64-block group), pool k=0..3,
// stencil LIFO k=3..0 as 16 double-buffered cp.async subtiles.
// ---------------------------------------------------------------------------
__global__ __launch_bounds__(256, 4) void fused_kernel(
        const float* __restrict__ x,
        const float* __restrict__ conv_w,
        const float* __restrict__ bn_gamma,
        const float* __restrict__ bn_beta,
        const float* __restrict__ bn_mean,
        const float* __restrict__ bn_var,
        const float* __restrict__ lamb_l,
        const float* __restrict__ lamb_h,
        const float* __restrict__ inside_all,
        float* __restrict__ out) {
    const int b    = blockIdx.x;
    const int g    = b >> 6;          // sample / group id
    const int r    = b & 63;          // rank within group
    const int tid  = threadIdx.x;
    const int warp = tid >> 5;
    const int lane = tid & 31;

    __shared__ __align__(16) float tiles[2][18 * TPITCH];
    __shared__ float ws[8];
    __shared__ float ps[C_];
    __shared__ float wlf[4][K2_];
    __shared__ float cst[4][3];       // A, Bc, lh1 per k

    unsigned int target = 0;
    if (tid == 0)
        target = (atomicAdd(&g_epoch_blk[b], 1u) + 1u) * 256u;

    // ---- pool: 4 quarter-plane items of sample g (k = 0..3) ----------------
    #pragma unroll 1
    for (int k = 0; k < 4; ++k) {
        const int item = g * 256 + r + 64 * k;
        const float4* xv = (const float4*)(x + (size_t)item * QELEMS);
        float s = 0.f;
        #pragma unroll
        for (int i = 0; i < 16; ++i) {
            float4 v = __ldg(&xv[tid + i * 256]);
            s += (v.x + v.y) + (v.z + v.w);
        }
        #pragma unroll
        for (int o = 16; o; o >>= 1) s += __shfl_down_sync(0xffffffffu, s, o);
        if (lane == 0) ws[warp] = s;
        __syncthreads();
        if (tid == 0)
            g_part[item] = ws[0] + ws[1] + ws[2] + ws[3]
                         + ws[4] + ws[5] + ws[6] + ws[7];
        __syncthreads();
    }

    // ---- group-local release + wait (64 blocks only) -----------------------
    if (tid == 0) {
        __threadfence();
        atomicAdd(&g_done[g], 4u);
        while (*((volatile unsigned int*)&g_done[g]) < target)
            __nanosleep(32);
    }
    __syncthreads();
    __threadfence();

    // ---- lf weights + per-channel constants (all 4 k at once) --------------
    if (tid < C_) {
        const float* p = g_part + (g * C_ + tid) * 4;
        ps[tid] = (__ldcg(p) + __ldcg(p + 1) + __ldcg(p + 2) + __ldcg(p + 3))
                  * (1.f / (H_ * W_));
    }
    __syncthreads();
    if (tid < 36) {
        const int k  = tid / 9;
        const int t9 = tid - 9 * k;
        const int c  = (r >> 2) + 16 * k;
        const int jj = (c >> 3) * K2_ + t9;
        const float* wv = conv_w + jj * C_;
        float acc = 0.f;
        #pragma unroll
        for (int cc = 0; cc < C_; ++cc) acc = fmaf(ps[cc], wv[cc], acc);
        const float inv = rsqrtf(bn_var[jj] + 1e-5f);
        const float v = (acc - bn_mean[jj]) * (bn_gamma[jj] * inv) + bn_beta[jj];
        wlf[k][t9] = tanhf(v);
        if (t9 == 0) {
            const float ll  = __ldg(lamb_l + c);
            const float ia  = __ldg(inside_all + c);
            cst[k][0] = (ia + 1.f) * ll;          // A
            cst[k][1] = -ia * ps[c] * ll;         // Bc
            cst[k][2] = __ldg(lamb_h + c) + 1.f;  // lh1
        }
    }
    __syncthreads();

    // ---- 16 subtiles, double-buffered cp.async, LIFO over k ----------------
    // idx -> k = 3 - (idx>>2) (LIFO over pooled quarters), sub = idx & 3
    const int tile_r = r & 3;              // 64-row tile within plane
    const int cbase  = r >> 2;
    const uint32_t t0a = (uint32_t)__cvta_generic_to_shared(&tiles[0][0]);
    const uint32_t t1a = (uint32_t)__cvta_generic_to_shared(&tiles[1][0]);

    #define PLANE_OF(idx)  ((size_t)(g * C_ + cbase + 16 * (3 - ((idx) >> 2))) * (H_ * W_))
    #define Y0_OF(idx)     (tile_r * 64 + ((idx) & 3) * 16)

    load_subtile(t0a, x + PLANE_OF(0), Y0_OF(0), tid);

    #pragma unroll 1
    for (int idx = 0; idx < 16; ++idx) {
        const int k = 3 - (idx >> 2);
        const uint32_t cur = (idx & 1) ? t1a : t0a;
        if (idx < 15) {
            const uint32_t nxt = (idx & 1) ? t0a : t1a;
            load_subtile(nxt, x + PLANE_OF(idx + 1), Y0_OF(idx + 1), tid);
            cp_wait<1>();
        } else {
            cp_wait<0>();
        }
        __syncthreads();
        float* ob0 = out + PLANE_OF(idx) + (size_t)Y0_OF(idx) * W_;
        compute_subtile((idx & 1) ? tiles[1] : tiles[0], ob0,
                        wlf[k], cst[k][0], cst[k][1], cst[k][2], warp, lane);
        __syncthreads();
    }
    #undef PLANE_OF
    #undef Y0_OF
}

// ---------------------------------------------------------------------------
extern "C" void kernel_launch(void* const* d_in, const int* in_sizes, int n_in,
                              void* d_out, int out_size) {
    const float* x          = (const float*)d_in[0];
    const float* conv_w     = (const float*)d_in[1];
    const float* bn_gamma   = (const float*)d_in[2];
    const float* bn_beta    = (const float*)d_in[3];
    const float* bn_mean    = (const float*)d_in[4];
    const float* bn_var     = (const float*)d_in[5];
    const float* lamb_l     = (const float*)d_in[6];
    const float* lamb_h     = (const float*)d_in[7];
    const float* inside_all = (const float*)d_in[8];
    float* out = (float*)d_out;

    fused_kernel<<<NBLK, 256>>>(x, conv_w, bn_gamma, bn_beta, bn_mean, bn_var,
                                lamb_l, lamb_h, inside_all, out);
}